// round 2
// baseline (speedup 1.0000x reference)
#include <cuda_runtime.h>
#include <cstdint>

// Problem constants (match reference)
#define NUM_USERS 150000
#define NUM_ITEMS 80000
#define N_NODES   230000
#define NNZ       5000000
#define DIM       64
#define NFLOATS   (N_NODES * DIM)        // 14,720,000 floats
#define NVEC4     (NFLOATS / 4)          // 3,680,000 float4

// Scratch ping-pong buffers (allocation-free: __device__ globals)
__device__ float g_bufA[NFLOATS];
__device__ float g_bufB[NFLOATS];

// ---------------------------------------------------------------------------
// init: out = x0 = concat(user, item); bufA = x0; bufB = 0
// ---------------------------------------------------------------------------
__global__ void init_kernel(const float4* __restrict__ user,
                            const float4* __restrict__ item,
                            float4* __restrict__ out) {
    int i = blockIdx.x * blockDim.x + threadIdx.x;
    if (i >= NVEC4) return;
    const int usz = NUM_USERS * DIM / 4;
    float4 v = (i < usz) ? user[i] : item[i - usz];
    out[i] = v;
    reinterpret_cast<float4*>(g_bufA)[i] = v;
    reinterpret_cast<float4*>(g_bufB)[i] = make_float4(0.f, 0.f, 0.f, 0.f);
}

// ---------------------------------------------------------------------------
// SpMM: dst[rows[e], :] += vals[e] * src[cols[e], :]
// 4 threads per edge, 4 x float4 (64B) per thread -> MLP=4 gathers.
// Edge index arrays use streaming loads (__ldcs) to avoid polluting L2,
// keeping the 118MB src+dst working set resident.
// DIR=0: A -> B ; DIR=1: B -> A
// ---------------------------------------------------------------------------
template <int DIR>
__global__ void __launch_bounds__(256)
spmm_kernel(const int*   __restrict__ rows,
            const int*   __restrict__ cols,
            const float* __restrict__ vals) {
    const float* __restrict__ src = DIR ? g_bufB : g_bufA;
    float*       __restrict__ dst = DIR ? g_bufA : g_bufB;

    int t = blockIdx.x * blockDim.x + threadIdx.x;
    int e = t >> 2;
    if (e >= NNZ) return;
    int sub = t & 3;                     // 0..3 -> 64-byte chunk of the row

    int   r = __ldcs(rows + e);
    int   c = __ldcs(cols + e);
    float v = __ldcs(vals + e);

    const float4* __restrict__ sp =
        reinterpret_cast<const float4*>(src + (size_t)c * DIM) + sub * 4;

    // batch 4 independent 16B gathers (MLP=4)
    float4 x0 = sp[0];
    float4 x1 = sp[1];
    float4 x2 = sp[2];
    float4 x3 = sp[3];

    float* dp = dst + (size_t)r * DIM + sub * 16;

    asm volatile("red.global.add.v4.f32 [%0], {%1, %2, %3, %4};"
                 :: "l"(dp +  0), "f"(x0.x * v), "f"(x0.y * v), "f"(x0.z * v), "f"(x0.w * v)
                 : "memory");
    asm volatile("red.global.add.v4.f32 [%0], {%1, %2, %3, %4};"
                 :: "l"(dp +  4), "f"(x1.x * v), "f"(x1.y * v), "f"(x1.z * v), "f"(x1.w * v)
                 : "memory");
    asm volatile("red.global.add.v4.f32 [%0], {%1, %2, %3, %4};"
                 :: "l"(dp +  8), "f"(x2.x * v), "f"(x2.y * v), "f"(x2.z * v), "f"(x2.w * v)
                 : "memory");
    asm volatile("red.global.add.v4.f32 [%0], {%1, %2, %3, %4};"
                 :: "l"(dp + 12), "f"(x3.x * v), "f"(x3.y * v), "f"(x3.z * v), "f"(x3.w * v)
                 : "memory");
}

// ---------------------------------------------------------------------------
// accumulate freshly computed layer into out, and zero the OTHER buffer
// (which becomes the next layer's destination). One pass instead of two.
// SRC=0: read B, zero A ; SRC=1: read A, zero B
// ---------------------------------------------------------------------------
template <int SRC>
__global__ void accum_zero_kernel(float4* __restrict__ out) {
    int i = blockIdx.x * blockDim.x + threadIdx.x;
    if (i >= NVEC4) return;
    const float4* __restrict__ fresh =
        reinterpret_cast<const float4*>(SRC ? g_bufA : g_bufB);
    float4* __restrict__ tozero =
        reinterpret_cast<float4*>(SRC ? g_bufB : g_bufA);
    float4 o = out[i];
    float4 f = fresh[i];
    o.x += f.x; o.y += f.y; o.z += f.z; o.w += f.w;
    out[i] = o;
    tozero[i] = make_float4(0.f, 0.f, 0.f, 0.f);
}

// final: out = (out + fresh(B)) * 0.25
__global__ void accum_scale_kernel(float4* __restrict__ out) {
    int i = blockIdx.x * blockDim.x + threadIdx.x;
    if (i >= NVEC4) return;
    const float4* __restrict__ fresh = reinterpret_cast<const float4*>(g_bufB);
    float4 o = out[i];
    float4 f = fresh[i];
    o.x = (o.x + f.x) * 0.25f;
    o.y = (o.y + f.y) * 0.25f;
    o.z = (o.z + f.z) * 0.25f;
    o.w = (o.w + f.w) * 0.25f;
    out[i] = o;
}

// ---------------------------------------------------------------------------
extern "C" void kernel_launch(void* const* d_in, const int* in_sizes, int n_in,
                              void* d_out, int out_size) {
    const float* user = (const float*)d_in[0];
    const float* item = (const float*)d_in[1];
    const int*   rows = (const int*)d_in[2];
    const int*   cols = (const int*)d_in[3];
    const float* vals = (const float*)d_in[4];
    float* out = (float*)d_out;

    const int TB = 256;
    const int elemGrid = (NVEC4 + TB - 1) / TB;                    // 14375
    const long long spmmThreads = (long long)NNZ * 4;              // 20M
    const int spmmGrid = (int)((spmmThreads + TB - 1) / TB);       // 78125

    // out = x0; A = x0; B = 0
    init_kernel<<<elemGrid, TB>>>((const float4*)user, (const float4*)item,
                                  (float4*)out);

    // layer 1: x1 = A*x0  (A -> B)
    spmm_kernel<0><<<spmmGrid, TB>>>(rows, cols, vals);
    accum_zero_kernel<0><<<elemGrid, TB>>>((float4*)out);  // out += B, zero A

    // layer 2: x2 (B -> A)
    spmm_kernel<1><<<spmmGrid, TB>>>(rows, cols, vals);
    accum_zero_kernel<1><<<elemGrid, TB>>>((float4*)out);  // out += A, zero B

    // layer 3: x3 (A -> B)
    spmm_kernel<0><<<spmmGrid, TB>>>(rows, cols, vals);
    accum_scale_kernel<<<elemGrid, TB>>>((float4*)out);    // out=(out+B)/4
}

// round 3
// speedup vs baseline: 1.5228x; 1.5228x over previous
#include <cuda_runtime.h>
#include <cstdint>

// Problem constants (match reference)
#define NUM_USERS 150000
#define NUM_ITEMS 80000
#define N_NODES   230000
#define NNZ       5000000
#define DIM       64
#define NFLOATS   (N_NODES * DIM)        // 14,720,000 floats
#define NVEC4     (NFLOATS / 4)          // 3,680,000 float4

#define EPT 4                            // edges per thread (ILP)
#define ECHUNK (NNZ / EPT)               // 1,250,000

// Scratch ping-pong buffers (allocation-free: __device__ globals)
__device__ float g_bufA[NFLOATS];
__device__ float g_bufB[NFLOATS];

// ---------------------------------------------------------------------------
// init: out = x0 = concat(user, item); bufA = x0; bufB = 0
// ---------------------------------------------------------------------------
__global__ void init_kernel(const float4* __restrict__ user,
                            const float4* __restrict__ item,
                            float4* __restrict__ out) {
    int i = blockIdx.x * blockDim.x + threadIdx.x;
    if (i >= NVEC4) return;
    const int usz = NUM_USERS * DIM / 4;
    float4 v = (i < usz) ? user[i] : item[i - usz];
    out[i] = v;
    reinterpret_cast<float4*>(g_bufA)[i] = v;
    reinterpret_cast<float4*>(g_bufB)[i] = make_float4(0.f, 0.f, 0.f, 0.f);
}

// ---------------------------------------------------------------------------
// SpMM: dst[rows[e], :] += vals[e] * src[cols[e], :]
// Layout: 16 threads per edge (lane sub = 16B chunk -> fully coalesced,
// 2 cache lines per edge per LDG wavefront), and EPT=4 edges per thread
// for MLP=4 on the gathers (hide ~250cyc L2 latency).
// Edge arrays streamed with __ldcs so the 118MB src/dst set stays in L2.
// DIR=0: A -> B ; DIR=1: B -> A
// ---------------------------------------------------------------------------
template <int DIR>
__global__ void __launch_bounds__(256)
spmm_kernel(const int*   __restrict__ rows,
            const int*   __restrict__ cols,
            const float* __restrict__ vals) {
    const float* __restrict__ src = DIR ? g_bufB : g_bufA;
    float*       __restrict__ dst = DIR ? g_bufA : g_bufB;

    int t = blockIdx.x * blockDim.x + threadIdx.x;
    int base = t >> 4;                   // 0 .. ECHUNK-1
    if (base >= ECHUNK) return;
    int sub = t & 15;                    // 16B chunk within the 256B row

    int e0 = base;
    int e1 = base + ECHUNK;
    int e2 = base + 2 * ECHUNK;
    int e3 = base + 3 * ECHUNK;

    // index loads: all 16 lanes of an edge-group read the same address
    // (broadcast), consecutive groups read consecutive edges.
    int   r0 = __ldcs(rows + e0), c0 = __ldcs(cols + e0);
    int   r1 = __ldcs(rows + e1), c1 = __ldcs(cols + e1);
    int   r2 = __ldcs(rows + e2), c2 = __ldcs(cols + e2);
    int   r3 = __ldcs(rows + e3), c3 = __ldcs(cols + e3);
    float v0 = __ldcs(vals + e0);
    float v1 = __ldcs(vals + e1);
    float v2 = __ldcs(vals + e2);
    float v3 = __ldcs(vals + e3);

    // 4 independent coalesced gathers (MLP=4)
    float4 x0 = *reinterpret_cast<const float4*>(src + (size_t)c0 * DIM + sub * 4);
    float4 x1 = *reinterpret_cast<const float4*>(src + (size_t)c1 * DIM + sub * 4);
    float4 x2 = *reinterpret_cast<const float4*>(src + (size_t)c2 * DIM + sub * 4);
    float4 x3 = *reinterpret_cast<const float4*>(src + (size_t)c3 * DIM + sub * 4);

    float* d0 = dst + (size_t)r0 * DIM + sub * 4;
    float* d1 = dst + (size_t)r1 * DIM + sub * 4;
    float* d2 = dst + (size_t)r2 * DIM + sub * 4;
    float* d3 = dst + (size_t)r3 * DIM + sub * 4;

    asm volatile("red.global.add.v4.f32 [%0], {%1, %2, %3, %4};"
                 :: "l"(d0), "f"(x0.x * v0), "f"(x0.y * v0), "f"(x0.z * v0), "f"(x0.w * v0)
                 : "memory");
    asm volatile("red.global.add.v4.f32 [%0], {%1, %2, %3, %4};"
                 :: "l"(d1), "f"(x1.x * v1), "f"(x1.y * v1), "f"(x1.z * v1), "f"(x1.w * v1)
                 : "memory");
    asm volatile("red.global.add.v4.f32 [%0], {%1, %2, %3, %4};"
                 :: "l"(d2), "f"(x2.x * v2), "f"(x2.y * v2), "f"(x2.z * v2), "f"(x2.w * v2)
                 : "memory");
    asm volatile("red.global.add.v4.f32 [%0], {%1, %2, %3, %4};"
                 :: "l"(d3), "f"(x3.x * v3), "f"(x3.y * v3), "f"(x3.z * v3), "f"(x3.w * v3)
                 : "memory");
}

// ---------------------------------------------------------------------------
// accumulate freshly computed layer into out, and zero the OTHER buffer
// (which becomes the next layer's destination). One pass instead of two.
// SRC=0: read B, zero A ; SRC=1: read A, zero B
// ---------------------------------------------------------------------------
template <int SRC>
__global__ void accum_zero_kernel(float4* __restrict__ out) {
    int i = blockIdx.x * blockDim.x + threadIdx.x;
    if (i >= NVEC4) return;
    const float4* __restrict__ fresh =
        reinterpret_cast<const float4*>(SRC ? g_bufA : g_bufB);
    float4* __restrict__ tozero =
        reinterpret_cast<float4*>(SRC ? g_bufB : g_bufA);
    float4 o = out[i];
    float4 f = fresh[i];
    o.x += f.x; o.y += f.y; o.z += f.z; o.w += f.w;
    out[i] = o;
    tozero[i] = make_float4(0.f, 0.f, 0.f, 0.f);
}

// final: out = (out + fresh(B)) * 0.25
__global__ void accum_scale_kernel(float4* __restrict__ out) {
    int i = blockIdx.x * blockDim.x + threadIdx.x;
    if (i >= NVEC4) return;
    const float4* __restrict__ fresh = reinterpret_cast<const float4*>(g_bufB);
    float4 o = out[i];
    float4 f = fresh[i];
    o.x = (o.x + f.x) * 0.25f;
    o.y = (o.y + f.y) * 0.25f;
    o.z = (o.z + f.z) * 0.25f;
    o.w = (o.w + f.w) * 0.25f;
    out[i] = o;
}

// ---------------------------------------------------------------------------
extern "C" void kernel_launch(void* const* d_in, const int* in_sizes, int n_in,
                              void* d_out, int out_size) {
    const float* user = (const float*)d_in[0];
    const float* item = (const float*)d_in[1];
    const int*   rows = (const int*)d_in[2];
    const int*   cols = (const int*)d_in[3];
    const float* vals = (const float*)d_in[4];
    float* out = (float*)d_out;

    const int TB = 256;
    const int elemGrid = (NVEC4 + TB - 1) / TB;                    // 14375
    const long long spmmThreads = (long long)ECHUNK * 16;          // 20M
    const int spmmGrid = (int)((spmmThreads + TB - 1) / TB);       // 78125

    // out = x0; A = x0; B = 0
    init_kernel<<<elemGrid, TB>>>((const float4*)user, (const float4*)item,
                                  (float4*)out);

    // layer 1: x1 = A*x0  (A -> B)
    spmm_kernel<0><<<spmmGrid, TB>>>(rows, cols, vals);
    accum_zero_kernel<0><<<elemGrid, TB>>>((float4*)out);  // out += B, zero A

    // layer 2: x2 (B -> A)
    spmm_kernel<1><<<spmmGrid, TB>>>(rows, cols, vals);
    accum_zero_kernel<1><<<elemGrid, TB>>>((float4*)out);  // out += A, zero B

    // layer 3: x3 (A -> B)
    spmm_kernel<0><<<spmmGrid, TB>>>(rows, cols, vals);
    accum_scale_kernel<<<elemGrid, TB>>>((float4*)out);    // out=(out+B)/4
}

// round 4
// speedup vs baseline: 1.5735x; 1.0333x over previous
#include <cuda_runtime.h>
#include <cstdint>

// Problem constants (match reference)
#define NUM_USERS 150000
#define NUM_ITEMS 80000
#define N_NODES   230000
#define NNZ       5000000
#define DIM       64
#define NFLOATS   (N_NODES * DIM)        // 14,720,000 floats
#define NVEC4     (NFLOATS / 4)          // 3,680,000 float4

#define EPT 4                            // edges per thread (ILP)
#define NGROUPS (NNZ / EPT)              // 1,250,000 groups of 4 consecutive edges

// Scratch ping-pong buffers (allocation-free: __device__ globals)
__device__ float g_bufA[NFLOATS];
__device__ float g_bufB[NFLOATS];

// ---------------------------------------------------------------------------
// init: out = x0 = concat(user, item); bufA = x0; bufB = 0
// ---------------------------------------------------------------------------
__global__ void init_kernel(const float4* __restrict__ user,
                            const float4* __restrict__ item,
                            float4* __restrict__ out) {
    int i = blockIdx.x * blockDim.x + threadIdx.x;
    if (i >= NVEC4) return;
    const int usz = NUM_USERS * DIM / 4;
    float4 v = (i < usz) ? user[i] : item[i - usz];
    out[i] = v;
    reinterpret_cast<float4*>(g_bufA)[i] = v;
    reinterpret_cast<float4*>(g_bufB)[i] = make_float4(0.f, 0.f, 0.f, 0.f);
}

// ---------------------------------------------------------------------------
// SpMM: dst[rows[e], :] += vals[e] * src[cols[e], :]
// 16 lanes per edge-group (lane sub = 16B chunk -> fully coalesced gathers),
// each thread handles 4 CONSECUTIVE edges so the index triple is loaded with
// three vectorized LDG.128s (int4/float4) instead of 12 scalar loads.
// Gathers for the 4 edges are independent -> MLP=4 hides L2 latency.
// Edge arrays streamed with __ldcs so the src/dst set stays L2-resident.
// DIR=0: A -> B ; DIR=1: B -> A
// ---------------------------------------------------------------------------
template <int DIR>
__global__ void __launch_bounds__(256)
spmm_kernel(const int4*   __restrict__ rows4,
            const int4*   __restrict__ cols4,
            const float4* __restrict__ vals4) {
    const float4* __restrict__ src =
        reinterpret_cast<const float4*>(DIR ? g_bufB : g_bufA);
    float* __restrict__ dst = DIR ? g_bufA : g_bufB;

    int t = blockIdx.x * blockDim.x + threadIdx.x;
    int g = t >> 4;                      // edge group (4 consecutive edges)
    if (g >= NGROUPS) return;
    int sub = t & 15;                    // 16B chunk within the 256B row

    // vectorized index loads (broadcast across the 16 lanes of a group)
    int4   r = __ldcs(rows4 + g);
    int4   c = __ldcs(cols4 + g);
    float4 v = __ldcs(vals4 + g);

    // 4 independent coalesced gathers (MLP=4); row stride = 16 float4s
    float4 x0 = src[(size_t)c.x * 16 + sub];
    float4 x1 = src[(size_t)c.y * 16 + sub];
    float4 x2 = src[(size_t)c.z * 16 + sub];
    float4 x3 = src[(size_t)c.w * 16 + sub];

    float* d0 = dst + (size_t)r.x * DIM + sub * 4;
    float* d1 = dst + (size_t)r.y * DIM + sub * 4;
    float* d2 = dst + (size_t)r.z * DIM + sub * 4;
    float* d3 = dst + (size_t)r.w * DIM + sub * 4;

    asm volatile("red.global.add.v4.f32 [%0], {%1, %2, %3, %4};"
                 :: "l"(d0), "f"(x0.x * v.x), "f"(x0.y * v.x), "f"(x0.z * v.x), "f"(x0.w * v.x)
                 : "memory");
    asm volatile("red.global.add.v4.f32 [%0], {%1, %2, %3, %4};"
                 :: "l"(d1), "f"(x1.x * v.y), "f"(x1.y * v.y), "f"(x1.z * v.y), "f"(x1.w * v.y)
                 : "memory");
    asm volatile("red.global.add.v4.f32 [%0], {%1, %2, %3, %4};"
                 :: "l"(d2), "f"(x2.x * v.z), "f"(x2.y * v.z), "f"(x2.z * v.z), "f"(x2.w * v.z)
                 : "memory");
    asm volatile("red.global.add.v4.f32 [%0], {%1, %2, %3, %4};"
                 :: "l"(d3), "f"(x3.x * v.w), "f"(x3.y * v.w), "f"(x3.z * v.w), "f"(x3.w * v.w)
                 : "memory");
}

// ---------------------------------------------------------------------------
// accumulate freshly computed layer into out, and zero the OTHER buffer
// (which becomes the next layer's destination). One pass instead of two.
// SRC=0: read B, zero A ; SRC=1: read A, zero B
// ---------------------------------------------------------------------------
template <int SRC>
__global__ void accum_zero_kernel(float4* __restrict__ out) {
    int i = blockIdx.x * blockDim.x + threadIdx.x;
    if (i >= NVEC4) return;
    const float4* __restrict__ fresh =
        reinterpret_cast<const float4*>(SRC ? g_bufA : g_bufB);
    float4* __restrict__ tozero =
        reinterpret_cast<float4*>(SRC ? g_bufB : g_bufA);
    float4 o = out[i];
    float4 f = fresh[i];
    o.x += f.x; o.y += f.y; o.z += f.z; o.w += f.w;
    out[i] = o;
    tozero[i] = make_float4(0.f, 0.f, 0.f, 0.f);
}

// final: out = (out + fresh(B)) * 0.25
__global__ void accum_scale_kernel(float4* __restrict__ out) {
    int i = blockIdx.x * blockDim.x + threadIdx.x;
    if (i >= NVEC4) return;
    const float4* __restrict__ fresh = reinterpret_cast<const float4*>(g_bufB);
    float4 o = out[i];
    float4 f = fresh[i];
    o.x = (o.x + f.x) * 0.25f;
    o.y = (o.y + f.y) * 0.25f;
    o.z = (o.z + f.z) * 0.25f;
    o.w = (o.w + f.w) * 0.25f;
    out[i] = o;
}

// ---------------------------------------------------------------------------
extern "C" void kernel_launch(void* const* d_in, const int* in_sizes, int n_in,
                              void* d_out, int out_size) {
    const float* user = (const float*)d_in[0];
    const float* item = (const float*)d_in[1];
    const int4*   rows4 = (const int4*)d_in[2];
    const int4*   cols4 = (const int4*)d_in[3];
    const float4* vals4 = (const float4*)d_in[4];
    float* out = (float*)d_out;

    const int TB = 256;
    const int elemGrid = (NVEC4 + TB - 1) / TB;                    // 14375
    const long long spmmThreads = (long long)NGROUPS * 16;         // 20M
    const int spmmGrid = (int)((spmmThreads + TB - 1) / TB);       // 78125

    // out = x0; A = x0; B = 0
    init_kernel<<<elemGrid, TB>>>((const float4*)user, (const float4*)item,
                                  (float4*)out);

    // layer 1: x1 = A*x0  (A -> B)
    spmm_kernel<0><<<spmmGrid, TB>>>(rows4, cols4, vals4);
    accum_zero_kernel<0><<<elemGrid, TB>>>((float4*)out);  // out += B, zero A

    // layer 2: x2 (B -> A)
    spmm_kernel<1><<<spmmGrid, TB>>>(rows4, cols4, vals4);
    accum_zero_kernel<1><<<elemGrid, TB>>>((float4*)out);  // out += A, zero B

    // layer 3: x3 (A -> B)
    spmm_kernel<0><<<spmmGrid, TB>>>(rows4, cols4, vals4);
    accum_scale_kernel<<<elemGrid, TB>>>((float4*)out);    // out=(out+B)/4
}

// round 5
// speedup vs baseline: 2.6774x; 1.7015x over previous
#include <cuda_runtime.h>
#include <cstdint>

// Problem constants (match reference)
#define NUM_USERS 150000
#define NUM_ITEMS 80000
#define N_NODES   230000
#define NNZ       5000000
#define DIM       64
#define NFLOATS   (N_NODES * DIM)        // 14,720,000 floats
#define NVEC4     (NFLOATS / 4)          // 3,680,000 float4

// scan config
#define N_SCAN    (N_NODES + 1)          // 230001
#define SCAN_TPB  256
#define SCAN_IPT  16
#define SCAN_EPB  (SCAN_TPB * SCAN_IPT)  // 4096
#define SCAN_NB   ((N_SCAN + SCAN_EPB - 1) / SCAN_EPB)  // 57

// Device-global scratch (allocation-free)
__device__ float g_x1[NFLOATS];
__device__ float g_x2[NFLOATS];
__device__ float g_x3[NFLOATS];
__device__ int   g_rowptr[N_SCAN];
__device__ int   g_cursor[N_NODES];
__device__ int   g_ecol[NNZ];
__device__ float g_eval[NNZ];
__device__ int   g_bsums[SCAN_NB];

// ---------------------------------------------------------------------------
// out = x0 = concat(user, item)
// ---------------------------------------------------------------------------
__global__ void init_kernel(const float4* __restrict__ user,
                            const float4* __restrict__ item,
                            float4* __restrict__ out) {
    int i = blockIdx.x * blockDim.x + threadIdx.x;
    if (i >= NVEC4) return;
    const int usz = NUM_USERS * DIM / 4;
    out[i] = (i < usz) ? user[i] : item[i - usz];
}

// ---------------------------------------------------------------------------
// CSR build: counting sort of edges by destination row
// ---------------------------------------------------------------------------
__global__ void zero_rowptr_kernel() {
    int i = blockIdx.x * blockDim.x + threadIdx.x;
    if (i < N_SCAN) g_rowptr[i] = 0;
}

__global__ void hist_kernel(const int* __restrict__ rows) {
    int e = blockIdx.x * blockDim.x + threadIdx.x;
    if (e >= NNZ) return;
    atomicAdd(&g_rowptr[__ldcs(rows + e) + 1], 1);   // RED.ADD, no return
}

// Block-level inclusive scan (4096 elems/block) + block sums
__global__ void scan1_kernel() {
    __shared__ int wsum[8];
    int tid = threadIdx.x;
    int base = blockIdx.x * SCAN_EPB + tid * SCAN_IPT;
    int v[SCAN_IPT];
    int run = 0;
#pragma unroll
    for (int k = 0; k < SCAN_IPT; k++) {
        int idx = base + k;
        int x = (idx < N_SCAN) ? g_rowptr[idx] : 0;
        run += x;
        v[k] = run;                       // inclusive within thread
    }
    int lane = tid & 31, wid = tid >> 5;
    int inc = run;
#pragma unroll
    for (int off = 1; off < 32; off <<= 1) {
        int y = __shfl_up_sync(0xffffffffu, inc, off);
        if (lane >= off) inc += y;
    }
    if (lane == 31) wsum[wid] = inc;
    __syncthreads();
    if (wid == 0) {
        int w = (lane < 8) ? wsum[lane] : 0;
#pragma unroll
        for (int off = 1; off < 8; off <<= 1) {
            int y = __shfl_up_sync(0xffffffffu, w, off);
            if (lane >= off) w += y;
        }
        if (lane < 8) wsum[lane] = w;     // inclusive warp sums
    }
    __syncthreads();
    int offset = (inc - run) + (wid > 0 ? wsum[wid - 1] : 0);
#pragma unroll
    for (int k = 0; k < SCAN_IPT; k++) {
        int idx = base + k;
        if (idx < N_SCAN) g_rowptr[idx] = v[k] + offset;
    }
    if (tid == 0) g_bsums[blockIdx.x] = wsum[7];
}

// serial exclusive scan of the 57 block sums (tiny)
__global__ void scan2_kernel() {
    if (threadIdx.x == 0 && blockIdx.x == 0) {
        int run = 0;
        for (int b = 0; b < SCAN_NB; b++) {
            int t = g_bsums[b];
            g_bsums[b] = run;
            run += t;
        }
    }
}

// add block offsets; also initialize cursor = rowptr
__global__ void scan3_kernel() {
    int i = blockIdx.x * blockDim.x + threadIdx.x;
    if (i >= N_SCAN) return;
    int val = g_rowptr[i] + g_bsums[i / SCAN_EPB];
    g_rowptr[i] = val;
    if (i < N_NODES) g_cursor[i] = val;
}

__global__ void scatter_kernel(const int* __restrict__ rows,
                               const int* __restrict__ cols,
                               const float* __restrict__ vals) {
    int e = blockIdx.x * blockDim.x + threadIdx.x;
    if (e >= NNZ) return;
    int r = __ldcs(rows + e);
    int pos = atomicAdd(&g_cursor[r], 1);
    g_ecol[pos] = __ldcs(cols + e);
    g_eval[pos] = __ldcs(vals + e);
}

// ---------------------------------------------------------------------------
// CSR SpMM, atomic-free: dst[r,:] = sum_{e in row r} val[e] * src[col[e],:]
// 16 lanes per row (lane = 16B chunk -> coalesced), register accumulation,
// unroll-4 over the row's edges for MLP=4 on the gathers, one STG.128 per
// lane at the end. No zeroing pass needed (every row fully overwritten).
// S: 0 = read d_out (x0), 1 = g_x1, 2 = g_x2.  D: 1/2/3 -> g_x1/g_x2/g_x3.
// ---------------------------------------------------------------------------
template <int S, int D>
__global__ void __launch_bounds__(256)
spmm_csr_kernel(const float4* __restrict__ out_src) {
    const float4* __restrict__ src =
        (S == 0) ? out_src
                 : reinterpret_cast<const float4*>(S == 1 ? g_x1 : g_x2);
    float4* __restrict__ dst =
        reinterpret_cast<float4*>(D == 1 ? g_x1 : (D == 2 ? g_x2 : g_x3));

    int t = blockIdx.x * blockDim.x + threadIdx.x;
    int r = t >> 4;
    if (r >= N_NODES) return;
    int sub = t & 15;

    int i   = g_rowptr[r];
    int end = g_rowptr[r + 1];

    float4 acc = make_float4(0.f, 0.f, 0.f, 0.f);

    for (; i + 4 <= end; i += 4) {
        int   c0 = g_ecol[i],     c1 = g_ecol[i + 1];
        int   c2 = g_ecol[i + 2], c3 = g_ecol[i + 3];
        float v0 = g_eval[i],     v1 = g_eval[i + 1];
        float v2 = g_eval[i + 2], v3 = g_eval[i + 3];
        float4 x0 = src[(size_t)c0 * 16 + sub];
        float4 x1 = src[(size_t)c1 * 16 + sub];
        float4 x2 = src[(size_t)c2 * 16 + sub];
        float4 x3 = src[(size_t)c3 * 16 + sub];
        acc.x = fmaf(v0, x0.x, acc.x); acc.y = fmaf(v0, x0.y, acc.y);
        acc.z = fmaf(v0, x0.z, acc.z); acc.w = fmaf(v0, x0.w, acc.w);
        acc.x = fmaf(v1, x1.x, acc.x); acc.y = fmaf(v1, x1.y, acc.y);
        acc.z = fmaf(v1, x1.z, acc.z); acc.w = fmaf(v1, x1.w, acc.w);
        acc.x = fmaf(v2, x2.x, acc.x); acc.y = fmaf(v2, x2.y, acc.y);
        acc.z = fmaf(v2, x2.z, acc.z); acc.w = fmaf(v2, x2.w, acc.w);
        acc.x = fmaf(v3, x3.x, acc.x); acc.y = fmaf(v3, x3.y, acc.y);
        acc.z = fmaf(v3, x3.z, acc.z); acc.w = fmaf(v3, x3.w, acc.w);
    }
    for (; i < end; i++) {
        int   c = g_ecol[i];
        float v = g_eval[i];
        float4 x = src[(size_t)c * 16 + sub];
        acc.x = fmaf(v, x.x, acc.x); acc.y = fmaf(v, x.y, acc.y);
        acc.z = fmaf(v, x.z, acc.z); acc.w = fmaf(v, x.w, acc.w);
    }

    dst[(size_t)r * 16 + sub] = acc;
}

// ---------------------------------------------------------------------------
// out = (out + x1 + x2 + x3) * 0.25
// ---------------------------------------------------------------------------
__global__ void merge_kernel(float4* __restrict__ out) {
    int i = blockIdx.x * blockDim.x + threadIdx.x;
    if (i >= NVEC4) return;
    const float4* __restrict__ a = reinterpret_cast<const float4*>(g_x1);
    const float4* __restrict__ b = reinterpret_cast<const float4*>(g_x2);
    const float4* __restrict__ c = reinterpret_cast<const float4*>(g_x3);
    float4 o = out[i];
    float4 f1 = a[i], f2 = b[i], f3 = c[i];
    o.x = (o.x + f1.x + f2.x + f3.x) * 0.25f;
    o.y = (o.y + f1.y + f2.y + f3.y) * 0.25f;
    o.z = (o.z + f1.z + f2.z + f3.z) * 0.25f;
    o.w = (o.w + f1.w + f2.w + f3.w) * 0.25f;
    out[i] = o;
}

// ---------------------------------------------------------------------------
extern "C" void kernel_launch(void* const* d_in, const int* in_sizes, int n_in,
                              void* d_out, int out_size) {
    const float* user = (const float*)d_in[0];
    const float* item = (const float*)d_in[1];
    const int*   rows = (const int*)d_in[2];
    const int*   cols = (const int*)d_in[3];
    const float* vals = (const float*)d_in[4];
    float* out = (float*)d_out;

    const int TB = 256;
    const int elemGrid  = (NVEC4 + TB - 1) / TB;           // 14375
    const int edgeGrid  = (NNZ + TB - 1) / TB;             // 19532
    const int scanGrid  = (N_SCAN + TB - 1) / TB;          // 899
    const int spmmGrid  = (N_NODES * 16 + TB - 1) / TB;    // 14375

    // CSR build (edge list identical across layers -> sort once)
    zero_rowptr_kernel<<<scanGrid, TB>>>();
    init_kernel<<<elemGrid, TB>>>((const float4*)user, (const float4*)item,
                                  (float4*)out);
    hist_kernel<<<edgeGrid, TB>>>(rows);
    scan1_kernel<<<SCAN_NB, SCAN_TPB>>>();
    scan2_kernel<<<1, 32>>>();
    scan3_kernel<<<scanGrid, TB>>>();
    scatter_kernel<<<edgeGrid, TB>>>(rows, cols, vals);

    // 3 atomic-free SpMM layers
    spmm_csr_kernel<0, 1><<<spmmGrid, TB>>>((const float4*)out);  // x0 -> x1
    spmm_csr_kernel<1, 2><<<spmmGrid, TB>>>(nullptr);             // x1 -> x2
    spmm_csr_kernel<2, 3><<<spmmGrid, TB>>>(nullptr);             // x2 -> x3

    // out = (x0 + x1 + x2 + x3) / 4
    merge_kernel<<<elemGrid, TB>>>((float4*)out);
}